// round 3
// baseline (speedup 1.0000x reference)
#include <cuda_runtime.h>
#include <cstdint>

// ---------------------------------------------------------------------------
// Decoder step: B=256, T=1, I=256, H=512, A=400, V=50000, OOV=50
// out: (256, 50050) float32
// ---------------------------------------------------------------------------

#define BATCH 256
#define IDIM  256
#define HDIM  512
#define ADIM  400
#define VDIM  50000
#define OUTC  50050

// ---------------- scratch (__device__ global, no allocs allowed) -----------
#define OFF_GATES  0            // 256*2048
#define OFF_H      524288       // 256*512
#define OFF_E      655360       // 256*400
#define OFF_ATT    757760       // 256*400
#define OFF_DECIN  860160       // 256*912
#define OFF_HIDDEN 1093632      // 256*1024
#define OFF_GEN    1355776      // 256
#define SCRATCH_TOTAL 1356032

__device__ float g_scratch[SCRATCH_TOTAL];

// ---------------------------------------------------------------------------
// helpers
// ---------------------------------------------------------------------------
__device__ __forceinline__ float sigf(float x) { return 1.f / (1.f + __expf(-x)); }

__device__ __forceinline__ float tf32r(float x) {
    uint32_t u;
    asm("cvt.rna.tf32.f32 %0, %1;" : "=r"(u) : "f"(x));
    return __uint_as_float(u);
}

__device__ __forceinline__ void mma_tf32(float* c, const uint32_t* a, const uint32_t* b) {
    asm volatile(
        "mma.sync.aligned.m16n8k8.row.col.f32.tf32.tf32.f32 "
        "{%0,%1,%2,%3}, {%4,%5,%6,%7}, {%8,%9}, {%0,%1,%2,%3};\n"
        : "+f"(c[0]), "+f"(c[1]), "+f"(c[2]), "+f"(c[3])
        : "r"(a[0]), "r"(a[1]), "r"(a[2]), "r"(a[3]), "r"(b[0]), "r"(b[1]));
}

// ---------------------------------------------------------------------------
// Generic small SIMT GEMM: C(M,N) = act( A(M,K)@W(N,K)^T [+ A2@W2^T] + b1 + b2 )
// 32x32 tile, 256 threads, 2x2 per thread.
// ---------------------------------------------------------------------------
__global__ __launch_bounds__(256) void gemm_simt(
    const float* __restrict__ A, const float* __restrict__ W,
    const float* __restrict__ A2, const float* __restrict__ W2,
    const float* __restrict__ b1, const float* __restrict__ b2,
    float* __restrict__ C, int M, int N, int K, int K2, int act)
{
    __shared__ float As[32][33];
    __shared__ float Ws[32][33];
    int n0 = blockIdx.x * 32, m0 = blockIdx.y * 32;
    int tid = threadIdx.x;
    int ty = tid >> 4, tx = tid & 15;
    float acc[2][2] = {{0.f, 0.f}, {0.f, 0.f}};

    for (int src = 0; src < 2; ++src) {
        const float* Ap = src ? A2 : A;
        const float* Wp = src ? W2 : W;
        int Kc = src ? K2 : K;
        if (Ap == nullptr || Kc == 0) continue;
        for (int k0 = 0; k0 < Kc; k0 += 32) {
            #pragma unroll
            for (int i = 0; i < 4; i++) {
                int e = tid + i * 256;
                int row = e >> 5, col = e & 31;
                float av = 0.f, wv = 0.f;
                if (m0 + row < M && k0 + col < Kc) av = Ap[(m0 + row) * Kc + k0 + col];
                if (n0 + row < N && k0 + col < Kc) wv = Wp[(n0 + row) * Kc + k0 + col];
                As[col][row] = av;   // [k][m]
                Ws[col][row] = wv;   // [k][n]
            }
            __syncthreads();
            #pragma unroll 8
            for (int k = 0; k < 32; k++) {
                float a0 = As[k][2 * ty], a1 = As[k][2 * ty + 1];
                float w0 = Ws[k][2 * tx], w1 = Ws[k][2 * tx + 1];
                acc[0][0] += a0 * w0; acc[0][1] += a0 * w1;
                acc[1][0] += a1 * w0; acc[1][1] += a1 * w1;
            }
            __syncthreads();
        }
    }
    #pragma unroll
    for (int i = 0; i < 2; i++)
        #pragma unroll
        for (int j = 0; j < 2; j++) {
            int r = m0 + 2 * ty + i, c = n0 + 2 * tx + j;
            if (r < M && c < N) {
                float bv = (b1 ? b1[c] : 0.f) + (b2 ? b2[c] : 0.f);
                float val = acc[i][j] + bv;
                if (act == 1) val = tanhf(val);
                C[r * N + c] = val;
            }
        }
}

// ---------------------------------------------------------------------------
// LSTM elementwise: h = sig(o)*tanh(sig(i)*tanh(g)); also fills dec_in[:,400:]
// ---------------------------------------------------------------------------
__global__ void lstm_h_kernel(const float* __restrict__ gates,
                              float* __restrict__ h, float* __restrict__ decin)
{
    int idx = blockIdx.x * blockDim.x + threadIdx.x;
    if (idx >= BATCH * HDIM) return;
    int b = idx >> 9, k = idx & 511;
    const float* g = gates + b * 2048;
    float ig = sigf(g[k]);
    float gg = tanhf(g[1024 + k]);
    float og = sigf(g[1536 + k]);
    float c = ig * gg;
    float hv = og * tanhf(c);
    h[idx] = hv;
    decin[b * 912 + 400 + k] = hv;
}

// ---------------------------------------------------------------------------
// attention = v * softmax(e) per row
// ---------------------------------------------------------------------------
__global__ void attn_softmax(const float* __restrict__ e, const float* __restrict__ v,
                             float* __restrict__ att)
{
    __shared__ float sh[128];
    int b = blockIdx.x, t = threadIdx.x;
    const float* er = e + b * ADIM;
    float m = -1e30f;
    for (int a = t; a < ADIM; a += 128) m = fmaxf(m, er[a]);
    sh[t] = m; __syncthreads();
    for (int s = 64; s > 0; s >>= 1) { if (t < s) sh[t] = fmaxf(sh[t], sh[t + s]); __syncthreads(); }
    m = sh[0]; __syncthreads();
    float sum = 0.f;
    for (int a = t; a < ADIM; a += 128) sum += __expf(er[a] - m);
    sh[t] = sum; __syncthreads();
    for (int s = 64; s > 0; s >>= 1) { if (t < s) sh[t] += sh[t + s]; __syncthreads(); }
    float inv = 1.f / sh[0];
    for (int a = t; a < ADIM; a += 128) att[b * ADIM + a] = v[a] * __expf(er[a] - m) * inv;
}

// ---------------------------------------------------------------------------
// context[b,:] = sum_a att[b,a]*enc[b,a,:]  -> dec_in[:, :400]; also gen[b]
// ---------------------------------------------------------------------------
__global__ __launch_bounds__(512) void context_gen(
    const float* __restrict__ att, const float* __restrict__ enc,
    const float* __restrict__ h, const float* __restrict__ x,
    const float* __restrict__ pg1, const float* __restrict__ pg2,
    const float* __restrict__ pg3, float* __restrict__ decin, float* __restrict__ gen)
{
    __shared__ float att_s[ADIM];
    __shared__ float red[512];
    int b = blockIdx.x, t = threadIdx.x;
    if (t < ADIM) att_s[t] = att[b * ADIM + t];
    __syncthreads();
    float ctx = 0.f;
    if (t < ADIM) {
        const float* ep = enc + (size_t)b * (ADIM * ADIM) + t;
        float s0 = 0.f, s1 = 0.f, s2 = 0.f, s3 = 0.f;
        for (int a = 0; a < ADIM; a += 4) {
            s0 += att_s[a]     * ep[a * ADIM];
            s1 += att_s[a + 1] * ep[(a + 1) * ADIM];
            s2 += att_s[a + 2] * ep[(a + 2) * ADIM];
            s3 += att_s[a + 3] * ep[(a + 3) * ADIM];
        }
        ctx = (s0 + s1) + (s2 + s3);
        decin[b * 912 + t] = ctx;
    }
    float p = h[b * HDIM + t] * pg3[t];
    if (t < ADIM) p += ctx * pg2[t];
    if (t < IDIM) p += x[b * IDIM + t] * pg1[t];
    red[t] = p; __syncthreads();
    for (int s = 256; s > 0; s >>= 1) { if (t < s) red[t] += red[t + s]; __syncthreads(); }
    if (t == 0) gen[b] = sigf(red[0]);
}

// ---------------------------------------------------------------------------
// fc2: logits(256, 50000) = hidden(256,1024) @ fc2_w(50000,1024)^T + fc2_b
// tf32 mma.sync, tile 128x128x16, 8 warps (2x4), 64x32 per warp.
// Writes directly into out rows (stride 50050).
// ---------------------------------------------------------------------------
__global__ __launch_bounds__(256) void fc2_mma(
    const float* __restrict__ A, const float* __restrict__ W,
    const float* __restrict__ bias, float* __restrict__ out)
{
    __shared__ float As[16][136];
    __shared__ float Bs[16][136];
    const int K = 1024;
    int n0 = blockIdx.x * 128, m0 = blockIdx.y * 128;
    int tid = threadIdx.x, lane = tid & 31, warp = tid >> 5;
    int wm = warp >> 2, wn = warp & 3;

    float acc[4][4][4];
    #pragma unroll
    for (int i = 0; i < 4; i++)
        #pragma unroll
        for (int j = 0; j < 4; j++)
            #pragma unroll
            for (int q = 0; q < 4; q++) acc[i][j][q] = 0.f;

    for (int k0 = 0; k0 < K; k0 += 16) {
        #pragma unroll
        for (int r = 0; r < 2; r++) {
            int idx = tid + r * 256;
            int row = idx >> 2, c4 = idx & 3;
            float4 va = *reinterpret_cast<const float4*>(A + (m0 + row) * K + k0 + c4 * 4);
            As[c4 * 4 + 0][row] = tf32r(va.x);
            As[c4 * 4 + 1][row] = tf32r(va.y);
            As[c4 * 4 + 2][row] = tf32r(va.z);
            As[c4 * 4 + 3][row] = tf32r(va.w);
            int wr = n0 + row;
            float4 vb = make_float4(0.f, 0.f, 0.f, 0.f);
            if (wr < VDIM) vb = *reinterpret_cast<const float4*>(W + (size_t)wr * K + k0 + c4 * 4);
            Bs[c4 * 4 + 0][row] = tf32r(vb.x);
            Bs[c4 * 4 + 1][row] = tf32r(vb.y);
            Bs[c4 * 4 + 2][row] = tf32r(vb.z);
            Bs[c4 * 4 + 3][row] = tf32r(vb.w);
        }
        __syncthreads();
        #pragma unroll
        for (int kk = 0; kk < 2; kk++) {
            uint32_t af[4][4], bf[4][2];
            int ar = wm * 64 + (lane >> 2);
            int ac = kk * 8 + (lane & 3);
            #pragma unroll
            for (int mt = 0; mt < 4; mt++) {
                int r = ar + mt * 16;
                af[mt][0] = __float_as_uint(As[ac][r]);
                af[mt][1] = __float_as_uint(As[ac][r + 8]);
                af[mt][2] = __float_as_uint(As[ac + 4][r]);
                af[mt][3] = __float_as_uint(As[ac + 4][r + 8]);
            }
            int bc = wn * 32 + (lane >> 2);
            int br = kk * 8 + (lane & 3);
            #pragma unroll
            for (int nt = 0; nt < 4; nt++) {
                bf[nt][0] = __float_as_uint(Bs[br][bc + nt * 8]);
                bf[nt][1] = __float_as_uint(Bs[br + 4][bc + nt * 8]);
            }
            #pragma unroll
            for (int mt = 0; mt < 4; mt++)
                #pragma unroll
                for (int nt = 0; nt < 4; nt++)
                    mma_tf32(acc[mt][nt], af[mt], bf[nt]);
        }
        __syncthreads();
    }

    int gr = lane >> 2, gc = (lane & 3) * 2;
    #pragma unroll
    for (int mt = 0; mt < 4; mt++) {
        int row = m0 + wm * 64 + mt * 16 + gr;
        #pragma unroll
        for (int nt = 0; nt < 4; nt++) {
            int col = n0 + wn * 32 + nt * 8 + gc;
            if (col < VDIM) {  // 50000 even -> col+1 also in range
                float b0 = bias[col], b1 = bias[col + 1];
                out[(size_t)row * OUTC + col]           = acc[mt][nt][0] + b0;
                out[(size_t)row * OUTC + col + 1]       = acc[mt][nt][1] + b1;
                out[(size_t)(row + 8) * OUTC + col]     = acc[mt][nt][2] + b0;
                out[(size_t)(row + 8) * OUTC + col + 1] = acc[mt][nt][3] + b1;
            }
        }
    }
}

// ---------------------------------------------------------------------------
// Per-row: softmax over 50000 logits (in-place), *gen, zero OOV cols, scatter.
// One block per row; scatter targets are row-local so no cross-block hazard.
// ---------------------------------------------------------------------------
__global__ __launch_bounds__(1024) void softmax_final(
    float* __restrict__ out, const float* __restrict__ gen,
    const float* __restrict__ att, const int* __restrict__ ids)
{
    __shared__ float sh[1024];
    int b = blockIdx.x, t = threadIdx.x;
    float* row = out + (size_t)b * OUTC;

    float m = -1e30f;
    for (int i = t; i < VDIM; i += 1024) m = fmaxf(m, row[i]);
    sh[t] = m; __syncthreads();
    for (int s = 512; s > 0; s >>= 1) { if (t < s) sh[t] = fmaxf(sh[t], sh[t + s]); __syncthreads(); }
    m = sh[0]; __syncthreads();

    float sum = 0.f;
    for (int i = t; i < VDIM; i += 1024) sum += __expf(row[i] - m);
    sh[t] = sum; __syncthreads();
    for (int s = 512; s > 0; s >>= 1) { if (t < s) sh[t] += sh[t + s]; __syncthreads(); }

    float g = gen[b];
    float inv = g / sh[0];
    for (int i = t; i < VDIM; i += 1024) row[i] = __expf(row[i] - m) * inv;
    if (t < 50) row[VDIM + t] = 0.f;
    __syncthreads();

    float gc = 1.f - g;
    if (t < ADIM) atomicAdd(&row[ids[b * ADIM + t]], gc * att[b * ADIM + t]);
}

// ---------------------------------------------------------------------------
// launch
// ---------------------------------------------------------------------------
extern "C" void kernel_launch(void* const* d_in, const int* in_sizes, int n_in,
                              void* d_out, int out_size)
{
    // Inputs (setup_inputs order). max_oov_nums may or may not appear as a
    // size-1 input at position 5; detect and shift.
    int s = (n_in > 5 && in_sizes[5] == 1) ? 1 : 0;
    const float* x         = (const float*)d_in[0];
    const float* enc_out   = (const float*)d_in[2];
    const float* enc_state = (const float*)d_in[4];
    const int*   ids       = (const int*)  d_in[5 + s];
    const float* W_ih      = (const float*)d_in[6 + s];
    const float* b_ih      = (const float*)d_in[8 + s];
    const float* b_hh      = (const float*)d_in[9 + s];
    const float* Wh_w      = (const float*)d_in[10 + s];
    const float* Wh_b      = (const float*)d_in[11 + s];
    const float* Ws_w      = (const float*)d_in[12 + s];
    const float* Ws_b      = (const float*)d_in[13 + s];
    const float* v         = (const float*)d_in[14 + s];
    const float* fc1_w     = (const float*)d_in[15 + s];
    const float* fc1_b     = (const float*)d_in[16 + s];
    const float* fc2_w     = (const float*)d_in[17 + s];
    const float* fc2_b     = (const float*)d_in[18 + s];
    const float* pg1       = (const float*)d_in[19 + s];
    const float* pg2       = (const float*)d_in[20 + s];
    const float* pg3       = (const float*)d_in[21 + s];
    float* out = (float*)d_out;

    void* sp = nullptr;
    cudaGetSymbolAddress(&sp, g_scratch);
    float* scr    = (float*)sp;
    float* gates  = scr + OFF_GATES;
    float* h      = scr + OFF_H;
    float* e      = scr + OFF_E;
    float* att    = scr + OFF_ATT;
    float* decin  = scr + OFF_DECIN;
    float* hidden = scr + OFF_HIDDEN;
    float* gen    = scr + OFF_GEN;

    // 1) gates = x0 @ W_ih^T + b_ih + b_hh        (256 x 2048, K=256)
    gemm_simt<<<dim3(64, 8), 256>>>(x, W_ih, nullptr, nullptr, b_ih, b_hh,
                                    gates, BATCH, 2048, IDIM, 0, 0);
    // 2) h from gates (also dec_in[:,400:912])
    lstm_h_kernel<<<512, 256>>>(gates, h, decin);
    // 3) e = tanh(es@Wh^T + h@Ws^T + Wh_b + Ws_b) (256 x 400, K=512 dual)
    gemm_simt<<<dim3(13, 8), 256>>>(enc_state, Wh_w, h, Ws_w, Wh_b, Ws_b,
                                    e, BATCH, ADIM, HDIM, HDIM, 1);
    // 4) attention = v * softmax(e)
    attn_softmax<<<256, 128>>>(e, v, att);
    // 5) context -> dec_in[:, :400]; gen
    context_gen<<<256, 512>>>(att, enc_out, h, x, pg1, pg2, pg3, decin, gen);
    // 6) hidden = dec_in @ fc1_w^T + fc1_b        (256 x 1024, K=912)
    gemm_simt<<<dim3(32, 8), 256>>>(decin, fc1_w, nullptr, nullptr, fc1_b, nullptr,
                                    hidden, BATCH, 1024, 912, 0, 0);
    // 7) logits -> out[:, :50000] (tf32 tensor GEMM)
    fc2_mma<<<dim3((VDIM + 127) / 128, 2), 256>>>(hidden, fc2_w, fc2_b, out);
    // 8) softmax * gen, zero OOV, scatter-add copy distribution
    softmax_final<<<256, 1024>>>(out, gen, att, ids);

    (void)out_size; (void)n_in;
}

// round 5
// speedup vs baseline: 1.0740x; 1.0740x over previous
#include <cuda_runtime.h>
#include <cstdint>

// ---------------------------------------------------------------------------
// Decoder step: B=256, T=1, I=256, H=512, A=400, V=50000, OOV=50
// out: (256, 50050) float32
// ---------------------------------------------------------------------------

#define BATCH 256
#define IDIM  256
#define HDIM  512
#define ADIM  400
#define VDIM  50000
#define OUTC  50050

// ---------------- scratch (__device__ global, no allocs allowed) -----------
#define OFF_GATES  0            // 256*2048
#define OFF_H      524288       // 256*512
#define OFF_E      655360       // 256*400
#define OFF_ATT    757760       // 256*400
#define OFF_DECIN  860160       // 256*912
#define OFF_HIDDEN 1093632      // 256*1024
#define OFF_GEN    1355776      // 256
#define OFF_CAT    1356032      // 256*1024  ([enc_state | h])
#define OFF_CATW   1618176      // 400*1024  ([Wh_w | Ws_w])
#define SCRATCH_TOTAL 2027776

__device__ float g_scratch[SCRATCH_TOTAL];

// ---------------------------------------------------------------------------
// helpers
// ---------------------------------------------------------------------------
__device__ __forceinline__ float sigf(float x) { return 1.f / (1.f + __expf(-x)); }

__device__ __forceinline__ float tf32r(float x) {
    uint32_t u;
    asm("cvt.rna.tf32.f32 %0, %1;" : "=r"(u) : "f"(x));
    return __uint_as_float(u);
}

__device__ __forceinline__ void mma_tf32(float* c, const uint32_t* a, const uint32_t* b) {
    asm volatile(
        "mma.sync.aligned.m16n8k8.row.col.f32.tf32.tf32.f32 "
        "{%0,%1,%2,%3}, {%4,%5,%6,%7}, {%8,%9}, {%0,%1,%2,%3};\n"
        : "+f"(c[0]), "+f"(c[1]), "+f"(c[2]), "+f"(c[3])
        : "r"(a[0]), "r"(a[1]), "r"(a[2]), "r"(a[3]), "r"(b[0]), "r"(b[1]));
}

// cp.async 16B with zero-fill predication (src-size 0 => 16 zero bytes)
__device__ __forceinline__ void cp16(uint32_t dst, const void* src, bool p) {
    int sz = p ? 16 : 0;
    asm volatile("cp.async.cg.shared.global [%0], [%1], 16, %2;\n"
                 :: "r"(dst), "l"(src), "r"(sz));
}
__device__ __forceinline__ void cp_commit() { asm volatile("cp.async.commit_group;\n" ::); }
__device__ __forceinline__ void cp_wait1()  { asm volatile("cp.async.wait_group 1;\n" ::); }

// ---------------------------------------------------------------------------
// Generic pipelined tf32 MMA GEMM:
//   C(M=256, N) = act( A(256,K) @ W(N,K)^T + b1 [+ b2] ), C row stride = ldc
// Tiles: BM=128 x BN=128 x BK=32, 3-stage cp.async pipeline, 256 threads,
// 8 warps (2 x 4), 64x32 warp tile, m16n8k8 tf32 mma.
// Out-of-range N rows and K tail are zero-filled via cp.async src-size=0.
// ---------------------------------------------------------------------------
#define BM 128
#define BN 128
#define BK 32
#define LDT 36                      // smem tile row stride (floats)
#define STAGE_F (2 * BM * LDT)      // floats per stage (A + B tiles) = 9216
#define MMA_SMEM_BYTES (3 * STAGE_F * 4)   // 110592

__global__ __launch_bounds__(256, 1) void mma_gemm(
    const float* __restrict__ A, const float* __restrict__ W,
    const float* __restrict__ b1, const float* __restrict__ b2,
    float* __restrict__ C, int N, int K, int ldc, int act)
{
    extern __shared__ float sm[];
    int tid = threadIdx.x, lane = tid & 31, warp = tid >> 5;
    int wm = warp >> 2, wn = warp & 3;
    int n0 = blockIdx.x * BN, m0 = blockIdx.y * BM;
    int NT = (K + BK - 1) / BK;

    // loader mapping: thread -> (row, 64B half-row)
    int arow = tid >> 1, half = tid & 1;
    const float* aptr = A + (size_t)(m0 + arow) * K;
    int nrow = n0 + arow;
    bool nok = nrow < N;
    const float* wptr = W + (size_t)(nok ? nrow : (N - 1)) * K;

    auto load_stage = [&](int slot, int k0) {
        float* As = sm + slot * STAGE_F;
        float* Bs = As + BM * LDT;
        uint32_t da = (uint32_t)__cvta_generic_to_shared(As + arow * LDT + half * 16);
        uint32_t db = (uint32_t)__cvta_generic_to_shared(Bs + arow * LDT + half * 16);
        #pragma unroll
        for (int j = 0; j < 4; j++) {
            int k = k0 + half * 16 + j * 4;
            bool pk = k < K;                 // K % 4 == 0 always here
            int ks = pk ? k : (K - 4);
            cp16(da + j * 16, aptr + ks, pk);
            cp16(db + j * 16, wptr + ks, pk && nok);
        }
    };

    float acc[4][4][4];
    #pragma unroll
    for (int i = 0; i < 4; i++)
        #pragma unroll
        for (int j = 0; j < 4; j++)
            #pragma unroll
            for (int q = 0; q < 4; q++) acc[i][j][q] = 0.f;

    load_stage(0, 0);
    cp_commit();
    if (NT > 1) load_stage(1, BK);
    cp_commit();

    for (int kt = 0; kt < NT; kt++) {
        cp_wait1();
        __syncthreads();
        int kn = kt + 2;
        if (kn < NT) load_stage(kn % 3, kn * BK);
        cp_commit();

        const float* As = sm + (kt % 3) * STAGE_F;
        const float* Bs = As + BM * LDT;
        #pragma unroll
        for (int kk = 0; kk < 4; kk++) {
            uint32_t af[4][4], bf[4][2];
            int ar = wm * 64 + (lane >> 2);
            int ac = kk * 8 + (lane & 3);
            #pragma unroll
            for (int mt = 0; mt < 4; mt++) {
                int r = ar + mt * 16;
                af[mt][0] = __float_as_uint(tf32r(As[r * LDT + ac]));
                af[mt][1] = __float_as_uint(tf32r(As[(r + 8) * LDT + ac]));
                af[mt][2] = __float_as_uint(tf32r(As[r * LDT + ac + 4]));
                af[mt][3] = __float_as_uint(tf32r(As[(r + 8) * LDT + ac + 4]));
            }
            int bc = wn * 32 + (lane >> 2);
            int br = kk * 8 + (lane & 3);
            #pragma unroll
            for (int nt = 0; nt < 4; nt++) {
                bf[nt][0] = __float_as_uint(tf32r(Bs[(bc + nt * 8) * LDT + br]));
                bf[nt][1] = __float_as_uint(tf32r(Bs[(bc + nt * 8) * LDT + br + 4]));
            }
            #pragma unroll
            for (int mt = 0; mt < 4; mt++)
                #pragma unroll
                for (int nt = 0; nt < 4; nt++)
                    mma_tf32(acc[mt][nt], af[mt], bf[nt]);
        }
        // no trailing sync needed: slot kt%3 is next written by loads issued
        // after the barrier at the top of iter kt+1.
    }

    int gr = lane >> 2, gc = (lane & 3) * 2;
    #pragma unroll
    for (int mt = 0; mt < 4; mt++) {
        int row = m0 + wm * 64 + mt * 16 + gr;
        #pragma unroll
        for (int nt = 0; nt < 4; nt++) {
            int col = n0 + wn * 32 + nt * 8 + gc;
            if (col < N) {   // N even, col even -> col+1 < N too
                float bb0 = b1[col]     + (b2 ? b2[col]     : 0.f);
                float bb1 = b1[col + 1] + (b2 ? b2[col + 1] : 0.f);
                float v00 = acc[mt][nt][0] + bb0, v01 = acc[mt][nt][1] + bb1;
                float v10 = acc[mt][nt][2] + bb0, v11 = acc[mt][nt][3] + bb1;
                if (act) { v00 = tanhf(v00); v01 = tanhf(v01);
                           v10 = tanhf(v10); v11 = tanhf(v11); }
                C[(size_t)row * ldc + col]             = v00;
                C[(size_t)row * ldc + col + 1]         = v01;
                C[(size_t)(row + 8) * ldc + col]       = v10;
                C[(size_t)(row + 8) * ldc + col + 1]   = v11;
            }
        }
    }
}

// ---------------------------------------------------------------------------
// pack [Wh_w | Ws_w] -> catw (400 x 1024)
// ---------------------------------------------------------------------------
__global__ void pack_w(const float* __restrict__ Wh, const float* __restrict__ Ws,
                       float* __restrict__ catw)
{
    int n = blockIdx.x, j = threadIdx.x;   // 400 blocks x 1024 threads
    catw[n * 1024 + j] = (j < HDIM) ? Wh[n * HDIM + j] : Ws[n * HDIM + j - HDIM];
}

// ---------------------------------------------------------------------------
// LSTM elementwise: h = sig(o)*tanh(sig(i)*tanh(g)); fills dec_in[:,400:] and
// cat = [enc_state | h]
// ---------------------------------------------------------------------------
__global__ void lstm_h_kernel(const float* __restrict__ gates,
                              const float* __restrict__ es,
                              float* __restrict__ h, float* __restrict__ decin,
                              float* __restrict__ cat)
{
    int idx = blockIdx.x * blockDim.x + threadIdx.x;
    if (idx >= BATCH * HDIM) return;
    int b = idx >> 9, k = idx & 511;
    const float* g = gates + b * 2048;
    float ig = sigf(g[k]);
    float gg = tanhf(g[1024 + k]);
    float og = sigf(g[1536 + k]);
    float c = ig * gg;
    float hv = og * tanhf(c);
    h[idx] = hv;
    decin[b * 912 + 400 + k] = hv;
    cat[b * 1024 + k] = es[idx];
    cat[b * 1024 + 512 + k] = hv;
}

// ---------------------------------------------------------------------------
// Fused: attention = v*softmax(e); context -> dec_in[:, :400]; gen[b]
// One block per batch row, 512 threads.
// ---------------------------------------------------------------------------
__global__ __launch_bounds__(512) void attn_context_gen(
    const float* __restrict__ e, const float* __restrict__ v,
    const float* __restrict__ enc, const float* __restrict__ h,
    const float* __restrict__ x,
    const float* __restrict__ pg1, const float* __restrict__ pg2,
    const float* __restrict__ pg3,
    float* __restrict__ att, float* __restrict__ decin, float* __restrict__ gen)
{
    __shared__ float att_s[ADIM];
    __shared__ float red[512];
    int b = blockIdx.x, t = threadIdx.x;

    // softmax over e row (400 valid)
    float ev = (t < ADIM) ? e[b * ADIM + t] : -1e30f;
    red[t] = ev; __syncthreads();
    for (int s = 256; s > 0; s >>= 1) { if (t < s) red[t] = fmaxf(red[t], red[t + s]); __syncthreads(); }
    float m = red[0]; __syncthreads();
    float ex = (t < ADIM) ? __expf(ev - m) : 0.f;
    red[t] = ex; __syncthreads();
    for (int s = 256; s > 0; s >>= 1) { if (t < s) red[t] += red[t + s]; __syncthreads(); }
    float inv = 1.f / red[0]; __syncthreads();

    float av = 0.f;
    if (t < ADIM) {
        av = v[t] * ex * inv;
        att_s[t] = av;
        att[b * ADIM + t] = av;
    }
    __syncthreads();

    // context
    float ctx = 0.f;
    if (t < ADIM) {
        const float* ep = enc + (size_t)b * (ADIM * ADIM) + t;
        float s0 = 0.f, s1 = 0.f, s2 = 0.f, s3 = 0.f;
        float s4 = 0.f, s5 = 0.f, s6 = 0.f, s7 = 0.f;
        #pragma unroll 2
        for (int a = 0; a < ADIM; a += 8) {
            s0 += att_s[a]     * ep[(a)     * ADIM];
            s1 += att_s[a + 1] * ep[(a + 1) * ADIM];
            s2 += att_s[a + 2] * ep[(a + 2) * ADIM];
            s3 += att_s[a + 3] * ep[(a + 3) * ADIM];
            s4 += att_s[a + 4] * ep[(a + 4) * ADIM];
            s5 += att_s[a + 5] * ep[(a + 5) * ADIM];
            s6 += att_s[a + 6] * ep[(a + 6) * ADIM];
            s7 += att_s[a + 7] * ep[(a + 7) * ADIM];
        }
        ctx = ((s0 + s1) + (s2 + s3)) + ((s4 + s5) + (s6 + s7));
        decin[b * 912 + t] = ctx;
    }

    // gen = sigmoid(ctx@pg2 + x@pg1 + h@pg3)
    float p = h[b * HDIM + t] * pg3[t];
    if (t < ADIM) p += ctx * pg2[t];
    if (t < IDIM) p += x[b * IDIM + t] * pg1[t];
    red[t] = p; __syncthreads();
    for (int s = 256; s > 0; s >>= 1) { if (t < s) red[t] += red[t + s]; __syncthreads(); }
    if (t == 0) gen[b] = sigf(red[0]);
}

// ---------------------------------------------------------------------------
// Per-row: online softmax over 50000 logits (in-place), *gen, zero OOV,
// scatter-add copy distribution. One block per row (row-local scatter).
// ---------------------------------------------------------------------------
__global__ __launch_bounds__(1024) void softmax_final(
    float* __restrict__ out, const float* __restrict__ gen,
    const float* __restrict__ att, const int* __restrict__ ids)
{
    __shared__ float shm[1024];
    __shared__ float shs[1024];
    int b = blockIdx.x, t = threadIdx.x;
    float* row = out + (size_t)b * OUTC;        // OUTC even -> 8B aligned rows
    float2* row2 = (float2*)row;

    // single online pass: max + sum
    float m = -1e30f, s = 0.f;
    for (int i = t; i < VDIM / 2; i += 1024) {
        float2 vv = row2[i];
        float lm = fmaxf(vv.x, vv.y);
        float nm = fmaxf(m, lm);
        s = s * __expf(m - nm) + __expf(vv.x - nm) + __expf(vv.y - nm);
        m = nm;
    }
    shm[t] = m; shs[t] = s; __syncthreads();
    for (int st = 512; st > 0; st >>= 1) {
        if (t < st) {
            float m2 = shm[t + st], s2 = shs[t + st];
            float nm = fmaxf(shm[t], m2);
            shs[t] = shs[t] * __expf(shm[t] - nm) + s2 * __expf(m2 - nm);
            shm[t] = nm;
        }
        __syncthreads();
    }
    float M = shm[0];
    float g = gen[b];
    float inv = g / shs[0];

    for (int i = t; i < VDIM / 2; i += 1024) {
        float2 vv = row2[i];
        vv.x = __expf(vv.x - M) * inv;
        vv.y = __expf(vv.y - M) * inv;
        row2[i] = vv;
    }
    if (t < 50) row[VDIM + t] = 0.f;
    __syncthreads();

    float gc = 1.f - g;
    if (t < ADIM) atomicAdd(&row[ids[b * ADIM + t]], gc * att[b * ADIM + t]);
}

// ---------------------------------------------------------------------------
// launch
// ---------------------------------------------------------------------------
extern "C" void kernel_launch(void* const* d_in, const int* in_sizes, int n_in,
                              void* d_out, int out_size)
{
    int s = (n_in > 5 && in_sizes[5] == 1) ? 1 : 0;
    const float* x         = (const float*)d_in[0];
    const float* enc_out   = (const float*)d_in[2];
    const float* enc_state = (const float*)d_in[4];
    const int*   ids       = (const int*)  d_in[5 + s];
    const float* W_ih      = (const float*)d_in[6 + s];
    const float* b_ih      = (const float*)d_in[8 + s];
    const float* b_hh      = (const float*)d_in[9 + s];
    const float* Wh_w      = (const float*)d_in[10 + s];
    const float* Wh_b      = (const float*)d_in[11 + s];
    const float* Ws_w      = (const float*)d_in[12 + s];
    const float* Ws_b      = (const float*)d_in[13 + s];
    const float* v         = (const float*)d_in[14 + s];
    const float* fc1_w     = (const float*)d_in[15 + s];
    const float* fc1_b     = (const float*)d_in[16 + s];
    const float* fc2_w     = (const float*)d_in[17 + s];
    const float* fc2_b     = (const float*)d_in[18 + s];
    const float* pg1       = (const float*)d_in[19 + s];
    const float* pg2       = (const float*)d_in[20 + s];
    const float* pg3       = (const float*)d_in[21 + s];
    float* out = (float*)d_out;

    void* sp = nullptr;
    cudaGetSymbolAddress(&sp, g_scratch);
    float* scr    = (float*)sp;
    float* gates  = scr + OFF_GATES;
    float* h      = scr + OFF_H;
    float* e      = scr + OFF_E;
    float* att    = scr + OFF_ATT;
    float* decin  = scr + OFF_DECIN;
    float* hidden = scr + OFF_HIDDEN;
    float* gen    = scr + OFF_GEN;
    float* cat    = scr + OFF_CAT;
    float* catw   = scr + OFF_CATW;

    cudaFuncSetAttribute(mma_gemm, cudaFuncAttributeMaxDynamicSharedMemorySize,
                         MMA_SMEM_BYTES);

    // 1) gates = x0 @ W_ih^T + b_ih + b_hh        (256 x 2048, K=256)
    mma_gemm<<<dim3(16, 2), 256, MMA_SMEM_BYTES>>>(x, W_ih, b_ih, b_hh,
                                                   gates, 2048, IDIM, 2048, 0);
    // 2) catw = [Wh_w | Ws_w]  (independent of 1)
    pack_w<<<400, 1024>>>(Wh_w, Ws_w, catw);
    // 3) h, dec_in[:,400:], cat=[es|h]
    lstm_h_kernel<<<512, 256>>>(gates, enc_state, h, decin, cat);
    // 4) e = tanh(cat @ catw^T + Wh_b + Ws_b)     (256 x 400, K=1024)
    mma_gemm<<<dim3(4, 2), 256, MMA_SMEM_BYTES>>>(cat, catw, Wh_b, Ws_b,
                                                  e, ADIM, 1024, ADIM, 1);
    // 5) attention softmax + context + gen (fused)
    attn_context_gen<<<256, 512>>>(e, v, enc_out, h, x, pg1, pg2, pg3,
                                   att, decin, gen);
    // 6) hidden = dec_in @ fc1_w^T + fc1_b        (256 x 1024, K=912)
    mma_gemm<<<dim3(8, 2), 256, MMA_SMEM_BYTES>>>(decin, fc1_w, fc1_b, nullptr,
                                                  hidden, 1024, 912, 1024, 0);
    // 7) logits -> out[:, :50000]                 (256 x 50000, K=1024)
    mma_gemm<<<dim3(391, 2), 256, MMA_SMEM_BYTES>>>(hidden, fc2_w, fc2_b, nullptr,
                                                    out, VDIM, 1024, OUTC, 0);
    // 8) softmax * gen, zero OOV, scatter-add copy distribution
    softmax_final<<<256, 1024>>>(out, gen, att, ids);

    (void)out_size; (void)n_in;
}

// round 8
// speedup vs baseline: 1.1407x; 1.0621x over previous
#include <cuda_runtime.h>
#include <cstdint>

// ---------------------------------------------------------------------------
// Decoder step: B=256, T=1, I=256, H=512, A=400, V=50000, OOV=50
// out: (256, 50050) float32
//
// ISA CEILING (learned R6): harness compiles at compute_103 (no 'a' suffix).
// tcgen05.*, TMA tensor ops, and all sm_103a-gated PTX are REJECTED by ptxas.
// Allowed: mma.sync (sm_80 style), cp.async, mbarrier, ldmatrix. Do not retry
// tcgen05 in future rounds.
//
// GEMMs use mma.sync tf32 (HW truncation, no cvt) with 2-stage cp.async,
// 72KB smem -> 2 CTAs/SM for latency hiding.
// ---------------------------------------------------------------------------

#define BATCH 256
#define IDIM  256
#define HDIM  512
#define ADIM  400
#define VDIM  50000
#define OUTC  50050

// ---------------- scratch (__device__ global, no allocs allowed) -----------
#define OFF_GATES  0            // 256*2048
#define OFF_H      524288       // 256*512
#define OFF_E      655360       // 256*400
#define OFF_ATT    757760       // 256*400
#define OFF_DECIN  860160       // 256*912
#define OFF_HIDDEN 1093632      // 256*1024
#define OFF_GEN    1355776      // 256
#define OFF_CAT    1356032      // 256*1024  ([enc_state | h])
#define OFF_CATW   1618176      // 400*1024  ([Wh_w | Ws_w])
#define SCRATCH_TOTAL 2027776

__device__ float g_scratch[SCRATCH_TOTAL];

// ---------------------------------------------------------------------------
// helpers
// ---------------------------------------------------------------------------
__device__ __forceinline__ float sigf(float x) { return 1.f / (1.f + __expf(-x)); }

__device__ __forceinline__ void mma_tf32(float* c, const uint32_t* a, const uint32_t* b) {
    asm volatile(
        "mma.sync.aligned.m16n8k8.row.col.f32.tf32.tf32.f32 "
        "{%0,%1,%2,%3}, {%4,%5,%6,%7}, {%8,%9}, {%0,%1,%2,%3};\n"
        : "+f"(c[0]), "+f"(c[1]), "+f"(c[2]), "+f"(c[3])
        : "r"(a[0]), "r"(a[1]), "r"(a[2]), "r"(a[3]), "r"(b[0]), "r"(b[1]));
}

// cp.async 16B with zero-fill predication (src-size 0 => 16 zero bytes)
__device__ __forceinline__ void cp16(uint32_t dst, const void* src, bool p) {
    int sz = p ? 16 : 0;
    asm volatile("cp.async.cg.shared.global [%0], [%1], 16, %2;\n"
                 :: "r"(dst), "l"(src), "r"(sz));
}
__device__ __forceinline__ void cp_commit() { asm volatile("cp.async.commit_group;\n" ::); }
__device__ __forceinline__ void cp_wait1()  { asm volatile("cp.async.wait_group 1;\n" ::); }

// ---------------------------------------------------------------------------
// Pipelined tf32 MMA GEMM:
//   C(256, N) = act( A(256,K) @ W(N,K)^T + b1 [+ b2] ), C row stride = ldc
// Tiles: BM=128 x BN=128 x BK=32, 2-stage cp.async, 256 threads,
// 8 warps (2x4), 64x32 warp tile, m16n8k8 tf32 mma.
// 2 stages -> 72KB smem -> 2 CTAs/SM (16 warps) for latency hiding.
// fp32->tf32 by HW truncation inside HMMA (no cvt instructions).
// Grid (2, NB): the two m-blocks sharing a W tile are adjacent bids ->
// co-resident -> W streamed from DRAM once.
// ---------------------------------------------------------------------------
#define BM 128
#define BN 128
#define BK 32
#define LDT 36                       // smem tile row stride (floats), conflict-free
#define STAGE_F (2 * BM * LDT)       // floats per stage (A + B) = 9216
#define MMA_SMEM_BYTES (2 * STAGE_F * 4)   // 73728

__global__ __launch_bounds__(256, 2) void mma_gemm(
    const float* __restrict__ A, const float* __restrict__ W,
    const float* __restrict__ b1, const float* __restrict__ b2,
    float* __restrict__ C, int N, int K, int ldc, int act)
{
    extern __shared__ float sm[];
    int tid = threadIdx.x, lane = tid & 31, warp = tid >> 5;
    int wm = warp >> 2, wn = warp & 3;
    int m0 = blockIdx.x * BM, n0 = blockIdx.y * BN;
    int NT = (K + BK - 1) / BK;       // K >= 256 here, so NT >= 8

    // loader mapping: thread -> (row, 64B half-row)
    int arow = tid >> 1, half = tid & 1;
    int mrow = m0 + arow; if (mrow >= BATCH) mrow = BATCH - 1;   // defensive clamp
    const float* aptr = A + (size_t)mrow * K;
    int nrow = n0 + arow;
    bool nok = nrow < N;
    const float* wptr = W + (size_t)(nok ? nrow : (N - 1)) * K;

    auto load_stage = [&](int slot, int k0) {
        float* As = sm + slot * STAGE_F;
        float* Bs = As + BM * LDT;
        uint32_t da = (uint32_t)__cvta_generic_to_shared(As + arow * LDT + half * 16);
        uint32_t db = (uint32_t)__cvta_generic_to_shared(Bs + arow * LDT + half * 16);
        #pragma unroll
        for (int j = 0; j < 4; j++) {
            int k = k0 + half * 16 + j * 4;
            bool pk = k < K;                 // K % 4 == 0 always here
            int ks = pk ? k : (K - 4);
            cp16(da + j * 16, aptr + ks, pk);
            cp16(db + j * 16, wptr + ks, pk && nok);
        }
    };

    float acc[4][4][4];
    #pragma unroll
    for (int i = 0; i < 4; i++)
        #pragma unroll
        for (int j = 0; j < 4; j++)
            #pragma unroll
            for (int q = 0; q < 4; q++) acc[i][j][q] = 0.f;

    load_stage(0, 0);
    cp_commit();
    load_stage(1, BK);
    cp_commit();

    for (int kt = 0; kt < NT; kt++) {
        cp_wait1();                    // chunk kt landed in slot kt&1
        __syncthreads();

        const float* As = sm + (kt & 1) * STAGE_F;
        const float* Bs = As + BM * LDT;
        #pragma unroll
        for (int kk = 0; kk < 4; kk++) {
            uint32_t af[4][4], bf[4][2];
            int ar = wm * 64 + (lane >> 2);
            int ac = kk * 8 + (lane & 3);
            #pragma unroll
            for (int mt = 0; mt < 4; mt++) {
                int r = ar + mt * 16;
                af[mt][0] = __float_as_uint(As[r * LDT + ac]);
                af[mt][1] = __float_as_uint(As[(r + 8) * LDT + ac]);
                af[mt][2] = __float_as_uint(As[r * LDT + ac + 4]);
                af[mt][3] = __float_as_uint(As[(r + 8) * LDT + ac + 4]);
            }
            int bc = wn * 32 + (lane >> 2);
            int br = kk * 8 + (lane & 3);
            #pragma unroll
            for (int nt = 0; nt < 4; nt++) {
                bf[nt][0] = __float_as_uint(Bs[(bc + nt * 8) * LDT + br]);
                bf[nt][1] = __float_as_uint(Bs[(bc + nt * 8) * LDT + br + 4]);
            }
            #pragma unroll
            for (int mt = 0; mt < 4; mt++)
                #pragma unroll
                for (int nt = 0; nt < 4; nt++)
                    mma_tf32(acc[mt][nt], af[mt], bf[nt]);
        }
        __syncthreads();               // slot kt&1 free for reuse
        int kn = kt + 2;
        if (kn < NT) { load_stage(kn & 1, kn * BK); cp_commit(); }
    }

    int gr = lane >> 2, gc = (lane & 3) * 2;
    #pragma unroll
    for (int mt = 0; mt < 4; mt++) {
        int row = m0 + wm * 64 + mt * 16 + gr;
        #pragma unroll
        for (int nt = 0; nt < 4; nt++) {
            int col = n0 + wn * 32 + nt * 8 + gc;
            if (col < N) {   // N even, col even -> col+1 < N too
                float bb0 = b1[col]     + (b2 ? b2[col]     : 0.f);
                float bb1 = b1[col + 1] + (b2 ? b2[col + 1] : 0.f);
                float v00 = acc[mt][nt][0] + bb0, v01 = acc[mt][nt][1] + bb1;
                float v10 = acc[mt][nt][2] + bb0, v11 = acc[mt][nt][3] + bb1;
                if (act) { v00 = tanhf(v00); v01 = tanhf(v01);
                           v10 = tanhf(v10); v11 = tanhf(v11); }
                C[(size_t)row * ldc + col]             = v00;
                C[(size_t)row * ldc + col + 1]         = v01;
                C[(size_t)(row + 8) * ldc + col]       = v10;
                C[(size_t)(row + 8) * ldc + col + 1]   = v11;
            }
        }
    }
}

// ---------------------------------------------------------------------------
// pack [Wh_w | Ws_w] -> catw (400 x 1024)
// ---------------------------------------------------------------------------
__global__ void pack_w(const float* __restrict__ Wh, const float* __restrict__ Ws,
                       float* __restrict__ catw)
{
    int n = blockIdx.x, j = threadIdx.x;
    catw[n * 1024 + j] = (j < HDIM) ? Wh[n * HDIM + j] : Ws[n * HDIM + j - HDIM];
}

// ---------------------------------------------------------------------------
// LSTM elementwise: h = sig(o)*tanh(sig(i)*tanh(g)); fills dec_in[:,400:] and
// cat = [enc_state | h]
// ---------------------------------------------------------------------------
__global__ void lstm_h_kernel(const float* __restrict__ gates,
                              const float* __restrict__ es,
                              float* __restrict__ h, float* __restrict__ decin,
                              float* __restrict__ cat)
{
    int idx = blockIdx.x * blockDim.x + threadIdx.x;
    if (idx >= BATCH * HDIM) return;
    int b = idx >> 9, k = idx & 511;
    const float* g = gates + b * 2048;
    float ig = sigf(g[k]);
    float gg = tanhf(g[1024 + k]);
    float og = sigf(g[1536 + k]);
    float c = ig * gg;
    float hv = og * tanhf(c);
    h[idx] = hv;
    decin[b * 912 + 400 + k] = hv;
    cat[b * 1024 + k] = es[idx];
    cat[b * 1024 + 512 + k] = hv;
}

// ---------------------------------------------------------------------------
// Fused: attention = v*softmax(e); context -> dec_in[:, :400]; gen[b]
// One block per batch row, 512 threads.
// ---------------------------------------------------------------------------
__global__ __launch_bounds__(512) void attn_context_gen(
    const float* __restrict__ e, const float* __restrict__ v,
    const float* __restrict__ enc, const float* __restrict__ h,
    const float* __restrict__ x,
    const float* __restrict__ pg1, const float* __restrict__ pg2,
    const float* __restrict__ pg3,
    float* __restrict__ att, float* __restrict__ decin, float* __restrict__ gen)
{
    __shared__ float att_s[ADIM];
    __shared__ float red[512];
    int b = blockIdx.x, t = threadIdx.x;

    float ev = (t < ADIM) ? e[b * ADIM + t] : -1e30f;
    red[t] = ev; __syncthreads();
    for (int s = 256; s > 0; s >>= 1) { if (t < s) red[t] = fmaxf(red[t], red[t + s]); __syncthreads(); }
    float m = red[0]; __syncthreads();
    float ex = (t < ADIM) ? __expf(ev - m) : 0.f;
    red[t] = ex; __syncthreads();
    for (int s = 256; s > 0; s >>= 1) { if (t < s) red[t] += red[t + s]; __syncthreads(); }
    float inv = 1.f / red[0]; __syncthreads();

    float av = 0.f;
    if (t < ADIM) {
        av = v[t] * ex * inv;
        att_s[t] = av;
        att[b * ADIM + t] = av;
    }
    __syncthreads();

    float ctx = 0.f;
    if (t < ADIM) {
        const float* ep = enc + (size_t)b * (ADIM * ADIM) + t;
        float s0 = 0.f, s1 = 0.f, s2 = 0.f, s3 = 0.f;
        float s4 = 0.f, s5 = 0.f, s6 = 0.f, s7 = 0.f;
        #pragma unroll 2
        for (int a = 0; a < ADIM; a += 8) {
            s0 += att_s[a]     * ep[(a)     * ADIM];
            s1 += att_s[a + 1] * ep[(a + 1) * ADIM];
            s2 += att_s[a + 2] * ep[(a + 2) * ADIM];
            s3 += att_s[a + 3] * ep[(a + 3) * ADIM];
            s4 += att_s[a + 4] * ep[(a + 4) * ADIM];
            s5 += att_s[a + 5] * ep[(a + 5) * ADIM];
            s6 += att_s[a + 6] * ep[(a + 6) * ADIM];
            s7 += att_s[a + 7] * ep[(a + 7) * ADIM];
        }
        ctx = ((s0 + s1) + (s2 + s3)) + ((s4 + s5) + (s6 + s7));
        decin[b * 912 + t] = ctx;
    }

    float p = h[b * HDIM + t] * pg3[t];
    if (t < ADIM) p += ctx * pg2[t];
    if (t < IDIM) p += x[b * IDIM + t] * pg1[t];
    red[t] = p; __syncthreads();
    for (int s = 256; s > 0; s >>= 1) { if (t < s) red[t] += red[t + s]; __syncthreads(); }
    if (t == 0) gen[b] = sigf(red[0]);
}

// ---------------------------------------------------------------------------
// Per-row: online softmax over 50000 logits (in-place), *gen, zero OOV,
// scatter-add copy distribution. One block per row (row-local scatter).
// ---------------------------------------------------------------------------
__global__ __launch_bounds__(1024) void softmax_final(
    float* __restrict__ out, const float* __restrict__ gen,
    const float* __restrict__ att, const int* __restrict__ ids)
{
    __shared__ float shm[1024];
    __shared__ float shs[1024];
    int b = blockIdx.x, t = threadIdx.x;
    float* row = out + (size_t)b * OUTC;
    float2* row2 = (float2*)row;

    float m = -1e30f, s = 0.f;
    for (int i = t; i < VDIM / 2; i += 1024) {
        float2 vv = row2[i];
        float lm = fmaxf(vv.x, vv.y);
        float nm = fmaxf(m, lm);
        s = s * __expf(m - nm) + __expf(vv.x - nm) + __expf(vv.y - nm);
        m = nm;
    }
    shm[t] = m; shs[t] = s; __syncthreads();
    for (int st = 512; st > 0; st >>= 1) {
        if (t < st) {
            float m2 = shm[t + st], s2 = shs[t + st];
            float nm = fmaxf(shm[t], m2);
            shs[t] = shs[t] * __expf(shm[t] - nm) + s2 * __expf(m2 - nm);
            shm[t] = nm;
        }
        __syncthreads();
    }
    float M = shm[0];
    float g = gen[b];
    float inv = g / shs[0];

    for (int i = t; i < VDIM / 2; i += 1024) {
        float2 vv = row2[i];
        vv.x = __expf(vv.x - M) * inv;
        vv.y = __expf(vv.y - M) * inv;
        row2[i] = vv;
    }
    if (t < 50) row[VDIM + t] = 0.f;
    __syncthreads();

    float gc = 1.f - g;
    if (t < ADIM) atomicAdd(&row[ids[b * ADIM + t]], gc * att[b * ADIM + t]);
}

// ---------------------------------------------------------------------------
// launch
// ---------------------------------------------------------------------------
extern "C" void kernel_launch(void* const* d_in, const int* in_sizes, int n_in,
                              void* d_out, int out_size)
{
    int s = (n_in > 5 && in_sizes[5] == 1) ? 1 : 0;
    const float* x         = (const float*)d_in[0];
    const float* enc_out   = (const float*)d_in[2];
    const float* enc_state = (const float*)d_in[4];
    const int*   ids       = (const int*)  d_in[5 + s];
    const float* W_ih      = (const float*)d_in[6 + s];
    const float* b_ih      = (const float*)d_in[8 + s];
    const float* b_hh      = (const float*)d_in[9 + s];
    const float* Wh_w      = (const float*)d_in[10 + s];
    const float* Wh_b      = (const float*)d_in[11 + s];
    const float* Ws_w      = (const float*)d_in[12 + s];
    const float* Ws_b      = (const float*)d_in[13 + s];
    const float* v         = (const float*)d_in[14 + s];
    const float* fc1_w     = (const float*)d_in[15 + s];
    const float* fc1_b     = (const float*)d_in[16 + s];
    const float* fc2_w     = (const float*)d_in[17 + s];
    const float* fc2_b     = (const float*)d_in[18 + s];
    const float* pg1       = (const float*)d_in[19 + s];
    const float* pg2       = (const float*)d_in[20 + s];
    const float* pg3       = (const float*)d_in[21 + s];
    float* out = (float*)d_out;

    void* sp = nullptr;
    cudaGetSymbolAddress(&sp, g_scratch);
    float* scr    = (float*)sp;
    float* gates  = scr + OFF_GATES;
    float* h      = scr + OFF_H;
    float* e      = scr + OFF_E;
    float* att    = scr + OFF_ATT;
    float* decin  = scr + OFF_DECIN;
    float* hidden = scr + OFF_HIDDEN;
    float* gen    = scr + OFF_GEN;
    float* cat    = scr + OFF_CAT;
    float* catw   = scr + OFF_CATW;

    cudaFuncSetAttribute(mma_gemm, cudaFuncAttributeMaxDynamicSharedMemorySize,
                         MMA_SMEM_BYTES);

    // 1) gates = x0 @ W_ih^T + b_ih + b_hh        (256 x 2048, K=256)
    mma_gemm<<<dim3(2, 16), 256, MMA_SMEM_BYTES>>>(x, W_ih, b_ih, b_hh,
                                                   gates, 2048, IDIM, 2048, 0);
    // 2) catw = [Wh_w | Ws_w]  (independent of 1)
    pack_w<<<400, 1024>>>(Wh_w, Ws_w, catw);
    // 3) h, dec_in[:,400:], cat=[es|h]
    lstm_h_kernel<<<512, 256>>>(gates, enc_state, h, decin, cat);
    // 4) e = tanh(cat @ catw^T + Wh_b + Ws_b)     (256 x 400, K=1024)
    mma_gemm<<<dim3(2, 4), 256, MMA_SMEM_BYTES>>>(cat, catw, Wh_b, Ws_b,
                                                  e, ADIM, 1024, ADIM, 1);
    // 5) attention softmax + context + gen (fused)
    attn_context_gen<<<256, 512>>>(e, v, enc_out, h, x, pg1, pg2, pg3,
                                   att, decin, gen);
    // 6) hidden = dec_in @ fc1_w^T + fc1_b        (256 x 1024, K=912)
    mma_gemm<<<dim3(2, 8), 256, MMA_SMEM_BYTES>>>(decin, fc1_w, fc1_b, nullptr,
                                                  hidden, 1024, 912, 1024, 0);
    // 7) logits -> out[:, :50000]                 (256 x 50000, K=1024)
    mma_gemm<<<dim3(2, 391), 256, MMA_SMEM_BYTES>>>(hidden, fc2_w, fc2_b, nullptr,
                                                    out, VDIM, 1024, OUTC, 0);
    // 8) softmax * gen, zero OOV, scatter-add copy distribution
    softmax_final<<<256, 1024>>>(out, gen, att, ids);

    (void)out_size; (void)n_in;
}

// round 9
// speedup vs baseline: 1.4933x; 1.3091x over previous
#include <cuda_runtime.h>
#include <cuda_fp16.h>
#include <cstdint>

// ---------------------------------------------------------------------------
// Decoder step: B=256, T=1, I=256, H=512, A=400, V=50000, OOV=50
// out: (256, 50050) float32
//
// ISA CEILING (learned R6): harness compiles at compute_103 (no 'a' suffix).
// tcgen05.*, TMA tensor ops are REJECTED by ptxas. Allowed: mma.sync (sm_80),
// ldmatrix, cp.async, mbarrier. Do not retry tcgen05.
//
// R9: fp16 m16n8k16 mma + ldmatrix from SW128-swizzled smem. fp16 mantissa
// (11 bits) == tf32; fp32 accumulate; values O(1) -> no range risk.
// Weights converted fp32->fp16 once per call; activations produced in fp16.
// ---------------------------------------------------------------------------

#define BATCH 256
#define IDIM  256
#define HDIM  512
#define ADIM  400
#define VDIM  50000
#define OUTC  50050

// ---------------- scratch (__device__ globals, no allocs allowed) ----------
__device__ __align__(16) __half g_fc2w_h[(size_t)VDIM * 1024];  // 100 MB
__device__ __align__(16) __half g_wih_h[2048 * IDIM];
__device__ __align__(16) __half g_catw_h[ADIM * 1024];
__device__ __align__(16) __half g_fc1w_h[1024 * 912];
__device__ __align__(16) __half g_x_h[BATCH * IDIM];
__device__ __align__(16) __half g_cat_h[BATCH * 1024];
__device__ __align__(16) __half g_decin_h[BATCH * 912];
__device__ __align__(16) __half g_hidden_h[BATCH * 1024];
__device__ __align__(16) float  g_gates[BATCH * 2048];
__device__ __align__(16) float  g_hbuf[BATCH * HDIM];
__device__ __align__(16) float  g_e[BATCH * ADIM];
__device__ __align__(16) float  g_att[BATCH * ADIM];
__device__ __align__(16) float  g_gen[BATCH];

// ---------------------------------------------------------------------------
// helpers
// ---------------------------------------------------------------------------
__device__ __forceinline__ float sigf(float x) { return 1.f / (1.f + __expf(-x)); }

__device__ __forceinline__ void mma_f16(float* c, const uint32_t* a, const uint32_t* b) {
    asm volatile(
        "mma.sync.aligned.m16n8k16.row.col.f32.f16.f16.f32 "
        "{%0,%1,%2,%3}, {%4,%5,%6,%7}, {%8,%9}, {%0,%1,%2,%3};\n"
        : "+f"(c[0]), "+f"(c[1]), "+f"(c[2]), "+f"(c[3])
        : "r"(a[0]), "r"(a[1]), "r"(a[2]), "r"(a[3]), "r"(b[0]), "r"(b[1]));
}

__device__ __forceinline__ void ldsm_x4(uint32_t* r, uint32_t addr) {
    asm volatile("ldmatrix.sync.aligned.m8n8.x4.shared.b16 {%0,%1,%2,%3}, [%4];"
                 : "=r"(r[0]), "=r"(r[1]), "=r"(r[2]), "=r"(r[3]) : "r"(addr));
}

// cp.async 16B with zero-fill predication (src-size 0 => 16 zero bytes)
__device__ __forceinline__ void cp16(uint32_t dst, const void* src, bool p) {
    int sz = p ? 16 : 0;
    asm volatile("cp.async.cg.shared.global [%0], [%1], 16, %2;\n"
                 :: "r"(dst), "l"(src), "r"(sz));
}
__device__ __forceinline__ void cp_commit() { asm volatile("cp.async.commit_group;\n" ::); }
__device__ __forceinline__ void cp_wait1()  { asm volatile("cp.async.wait_group 1;\n" ::); }
__device__ __forceinline__ void cp_wait0()  { asm volatile("cp.async.wait_group 0;\n" ::); }

// ---------------------------------------------------------------------------
// fp16 GEMM: C(256,N) = act( A(256,K)h @ W(N,K)h^T + b1 [+ b2] )
// BM=128 BN=128 BK=64(halves), 2-stage cp.async (32KB/stage, 64KB total ->
// 2 CTAs/SM). 256 thr, 8 warps (2x4), warp tile 64x32.
// smem rows = 128B (64 halves) with SW128 granule swizzle c^(row&7) ->
// conflict-free ldmatrix + stores. Fragments via ldmatrix.x4:
//   per k16 step: 4 LDSM(A) + 2 LDSM(B) + 16 HMMA.
// Grid (2, NB): 2 m-blocks sharing a W tile adjacent -> co-resident -> W
// streamed from DRAM once. outh: store C as fp16 (feeds next GEMM).
// ---------------------------------------------------------------------------
#define HG_STAGE 32768
#define HG_SMEM  (2 * HG_STAGE)

__global__ __launch_bounds__(256, 2) void hgemm(
    const __half* __restrict__ A, const __half* __restrict__ W,
    const float* __restrict__ b1, const float* __restrict__ b2,
    void* __restrict__ Cv, int N, int K, int ldc, int act, int outh)
{
    extern __shared__ char smem[];
    uint32_t sb = (uint32_t)__cvta_generic_to_shared(smem);
    int tid = threadIdx.x, lane = tid & 31, warp = tid >> 5;
    int wm = warp >> 2, wn = warp & 3;
    int m0 = blockIdx.x * 128, n0 = blockIdx.y * 128;
    int NT = (K + 63) / 64;

    // ---- loader: threads 0-127 -> A row t; 128-255 -> B row t-128 ----
    int lrow = tid & 127;
    bool isB = tid >= 128;
    bool rowok;
    const __half* gptr;
    if (!isB) { gptr = A + (size_t)(m0 + lrow) * K; rowok = true; }
    else { int nr = n0 + lrow; rowok = nr < N; gptr = W + (size_t)(rowok ? nr : 0) * K; }
    uint32_t dbase = sb + (isB ? 16384u : 0u) + (uint32_t)lrow * 128u;
    int lrs = lrow & 7;

    auto load_stage = [&](int slot, int k0) {
        uint32_t d = dbase + slot * HG_STAGE;
        #pragma unroll
        for (int c = 0; c < 8; c++) {
            int k = k0 + c * 8;
            bool pk = rowok && (k + 8 <= K);
            cp16(d + (uint32_t)((c ^ lrs) << 4), gptr + k, pk);
        }
    };

    // ---- fragment address components ----
    int row_a = wm * 64 + (lane & 15);
    int ka = lane >> 4;             // k-half for A ldmatrix
    int rs_a = row_a & 7;
    int row_b = wn * 32 + ((lane >> 4) << 3) + (lane & 7);
    int kb = (lane >> 3) & 1;       // k-half for B ldmatrix
    int rs_b = lane & 7;

    float acc[4][4][4];
    #pragma unroll
    for (int i = 0; i < 4; i++)
        #pragma unroll
        for (int j = 0; j < 4; j++)
            #pragma unroll
            for (int q = 0; q < 4; q++) acc[i][j][q] = 0.f;

    load_stage(0, 0);  cp_commit();
    load_stage(1, 64); cp_commit();

    for (int kt = 0; kt < NT; kt++) {
        if (kt + 1 < NT) cp_wait1(); else cp_wait0();
        __syncthreads();

        uint32_t sA = sb + (kt & 1) * HG_STAGE;
        uint32_t sB = sA + 16384u;
        #pragma unroll
        for (int kk = 0; kk < 4; kk++) {
            uint32_t af[4][4], bf[4][2];
            uint32_t offA = (uint32_t)((((kk * 2 + ka) ^ rs_a) << 4));
            #pragma unroll
            for (int mt = 0; mt < 4; mt++)
                ldsm_x4(af[mt], sA + (uint32_t)((row_a + mt * 16) * 128) + offA);
            uint32_t offB = (uint32_t)((((kk * 2 + kb) ^ rs_b) << 4));
            #pragma unroll
            for (int p = 0; p < 2; p++) {
                uint32_t r[4];
                ldsm_x4(r, sB + (uint32_t)((row_b + p * 16) * 128) + offB);
                bf[2 * p][0] = r[0]; bf[2 * p][1] = r[1];
                bf[2 * p + 1][0] = r[2]; bf[2 * p + 1][1] = r[3];
            }
            #pragma unroll
            for (int mt = 0; mt < 4; mt++)
                #pragma unroll
                for (int nt = 0; nt < 4; nt++)
                    mma_f16(acc[mt][nt], af[mt], bf[nt]);
        }
        __syncthreads();
        int kn = kt + 2;
        if (kn < NT) { load_stage(kt & 1, kn * 64); cp_commit(); }
    }

    // ---- epilogue ----
    int gr = lane >> 2, gc = (lane & 3) * 2;
    #pragma unroll
    for (int mt = 0; mt < 4; mt++) {
        int row = m0 + wm * 64 + mt * 16 + gr;
        #pragma unroll
        for (int nt = 0; nt < 4; nt++) {
            int col = n0 + wn * 32 + nt * 8 + gc;
            if (col < N) {   // N even, col even -> col+1 < N too
                float bb0 = b1[col]     + (b2 ? b2[col]     : 0.f);
                float bb1 = b1[col + 1] + (b2 ? b2[col + 1] : 0.f);
                float v00 = acc[mt][nt][0] + bb0, v01 = acc[mt][nt][1] + bb1;
                float v10 = acc[mt][nt][2] + bb0, v11 = acc[mt][nt][3] + bb1;
                if (act) { v00 = tanhf(v00); v01 = tanhf(v01);
                           v10 = tanhf(v10); v11 = tanhf(v11); }
                if (outh) {
                    __half* Ch = (__half*)Cv;
                    *(__half2*)&Ch[(size_t)row * ldc + col]       = __floats2half2_rn(v00, v01);
                    *(__half2*)&Ch[(size_t)(row + 8) * ldc + col] = __floats2half2_rn(v10, v11);
                } else {
                    float* C = (float*)Cv;
                    *(float2*)&C[(size_t)row * ldc + col]       = make_float2(v00, v01);
                    *(float2*)&C[(size_t)(row + 8) * ldc + col] = make_float2(v10, v11);
                }
            }
        }
    }
}

// ---------------------------------------------------------------------------
// fp32 -> fp16 convert (vectorized, 8 elems/thread)
// ---------------------------------------------------------------------------
__global__ void f2h(const float* __restrict__ in, __half* __restrict__ out, int n)
{
    int i = (blockIdx.x * blockDim.x + threadIdx.x) * 8;
    if (i >= n) return;
    float4 a = *(const float4*)(in + i);
    float4 b = *(const float4*)(in + i + 4);
    __half2 h[4] = { __floats2half2_rn(a.x, a.y), __floats2half2_rn(a.z, a.w),
                     __floats2half2_rn(b.x, b.y), __floats2half2_rn(b.z, b.w) };
    *(uint4*)(out + i) = *(uint4*)h;
}

// pack [Wh_w | Ws_w] -> catw_h (400 x 1024) fp16
__global__ void pack_catw(const float* __restrict__ Wh, const float* __restrict__ Ws,
                          __half* __restrict__ catw)
{
    int n = blockIdx.x, t = threadIdx.x;        // 400 blocks x 128 threads
    int j = t * 8;
    const float* src = (j < HDIM) ? (Wh + n * HDIM + j) : (Ws + n * HDIM + (j - HDIM));
    float4 a = *(const float4*)src;
    float4 b = *(const float4*)(src + 4);
    __half2 h[4] = { __floats2half2_rn(a.x, a.y), __floats2half2_rn(a.z, a.w),
                     __floats2half2_rn(b.x, b.y), __floats2half2_rn(b.z, b.w) };
    *(uint4*)(catw + n * 1024 + j) = *(uint4*)h;
}

// ---------------------------------------------------------------------------
// LSTM elementwise: h = sig(o)*tanh(sig(i)*tanh(g)); fills decin_h[:,400:]
// (fp16) and cat_h = [enc_state | h] (fp16); h kept fp32 for gen.
// ---------------------------------------------------------------------------
__global__ void lstm_h_kernel(const float* __restrict__ gates,
                              const float* __restrict__ es,
                              float* __restrict__ h, __half* __restrict__ decin_h,
                              __half* __restrict__ cat_h)
{
    int idx = blockIdx.x * blockDim.x + threadIdx.x;
    if (idx >= BATCH * HDIM) return;
    int b = idx >> 9, k = idx & 511;
    const float* g = gates + b * 2048;
    float ig = sigf(g[k]);
    float gg = tanhf(g[1024 + k]);
    float og = sigf(g[1536 + k]);
    float c = ig * gg;
    float hv = og * tanhf(c);
    h[idx] = hv;
    decin_h[b * 912 + 400 + k] = __float2half_rn(hv);
    cat_h[b * 1024 + k] = __float2half_rn(es[idx]);
    cat_h[b * 1024 + 512 + k] = __float2half_rn(hv);
}

// ---------------------------------------------------------------------------
// Fused: attention = v*softmax(e); context -> decin_h[:, :400] (fp16); gen[b]
// One block per batch row, 512 threads.
// ---------------------------------------------------------------------------
__global__ __launch_bounds__(512) void attn_context_gen(
    const float* __restrict__ e, const float* __restrict__ v,
    const float* __restrict__ enc, const float* __restrict__ h,
    const float* __restrict__ x,
    const float* __restrict__ pg1, const float* __restrict__ pg2,
    const float* __restrict__ pg3,
    float* __restrict__ att, __half* __restrict__ decin_h, float* __restrict__ gen)
{
    __shared__ float att_s[ADIM];
    __shared__ float red[512];
    int b = blockIdx.x, t = threadIdx.x;

    float ev = (t < ADIM) ? e[b * ADIM + t] : -1e30f;
    red[t] = ev; __syncthreads();
    for (int s = 256; s > 0; s >>= 1) { if (t < s) red[t] = fmaxf(red[t], red[t + s]); __syncthreads(); }
    float m = red[0]; __syncthreads();
    float ex = (t < ADIM) ? __expf(ev - m) : 0.f;
    red[t] = ex; __syncthreads();
    for (int s = 256; s > 0; s >>= 1) { if (t < s) red[t] += red[t + s]; __syncthreads(); }
    float inv = 1.f / red[0]; __syncthreads();

    float av = 0.f;
    if (t < ADIM) {
        av = v[t] * ex * inv;
        att_s[t] = av;
        att[b * ADIM + t] = av;
    }
    __syncthreads();

    float ctx = 0.f;
    if (t < ADIM) {
        const float* ep = enc + (size_t)b * (ADIM * ADIM) + t;
        float s0 = 0.f, s1 = 0.f, s2 = 0.f, s3 = 0.f;
        float s4 = 0.f, s5 = 0.f, s6 = 0.f, s7 = 0.f;
        #pragma unroll 2
        for (int a = 0; a < ADIM; a += 8) {
            s0 += att_s[a]     * ep[(a)     * ADIM];
            s1 += att_s[a + 1] * ep[(a + 1) * ADIM];
            s2 += att_s[a + 2] * ep[(a + 2) * ADIM];
            s3 += att_s[a + 3] * ep[(a + 3) * ADIM];
            s4 += att_s[a + 4] * ep[(a + 4) * ADIM];
            s5 += att_s[a + 5] * ep[(a + 5) * ADIM];
            s6 += att_s[a + 6] * ep[(a + 6) * ADIM];
            s7 += att_s[a + 7] * ep[(a + 7) * ADIM];
        }
        ctx = ((s0 + s1) + (s2 + s3)) + ((s4 + s5) + (s6 + s7));
        decin_h[b * 912 + t] = __float2half_rn(ctx);
    }

    float p = h[b * HDIM + t] * pg3[t];
    if (t < ADIM) p += ctx * pg2[t];
    if (t < IDIM) p += x[b * IDIM + t] * pg1[t];
    red[t] = p; __syncthreads();
    for (int s = 256; s > 0; s >>= 1) { if (t < s) red[t] += red[t + s]; __syncthreads(); }
    if (t == 0) gen[b] = sigf(red[0]);
}

// ---------------------------------------------------------------------------
// Per-row: online softmax over 50000 logits (in-place), *gen, zero OOV,
// scatter-add copy distribution. One block per row (row-local scatter).
// ---------------------------------------------------------------------------
__global__ __launch_bounds__(1024) void softmax_final(
    float* __restrict__ out, const float* __restrict__ gen,
    const float* __restrict__ att, const int* __restrict__ ids)
{
    __shared__ float shm[1024];
    __shared__ float shs[1024];
    int b = blockIdx.x, t = threadIdx.x;
    float* row = out + (size_t)b * OUTC;
    float2* row2 = (float2*)row;

    float m = -1e30f, s = 0.f;
    for (int i = t; i < VDIM / 2; i += 1024) {
        float2 vv = row2[i];
        float lm = fmaxf(vv.x, vv.y);
        float nm = fmaxf(m, lm);
        s = s * __expf(m - nm) + __expf(vv.x - nm) + __expf(vv.y - nm);
        m = nm;
    }
    shm[t] = m; shs[t] = s; __syncthreads();
    for (int st = 512; st > 0; st >>= 1) {
        if (t < st) {
            float m2 = shm[t + st], s2 = shs[t + st];
            float nm = fmaxf(shm[t], m2);
            shs[t] = shs[t] * __expf(shm[t] - nm) + s2 * __expf(m2 - nm);
            shm[t] = nm;
        }
        __syncthreads();
    }
    float M = shm[0];
    float g = gen[b];
    float inv = g / shs[0];

    for (int i = t; i < VDIM / 2; i += 1024) {
        float2 vv = row2[i];
        vv.x = __expf(vv.x - M) * inv;
        vv.y = __expf(vv.y - M) * inv;
        row2[i] = vv;
    }
    if (t < 50) row[VDIM + t] = 0.f;
    __syncthreads();

    float gc = 1.f - g;
    if (t < ADIM) atomicAdd(&row[ids[b * ADIM + t]], gc * att[b * ADIM + t]);
}

// ---------------------------------------------------------------------------
// launch
// ---------------------------------------------------------------------------
extern "C" void kernel_launch(void* const* d_in, const int* in_sizes, int n_in,
                              void* d_out, int out_size)
{
    int s = (n_in > 5 && in_sizes[5] == 1) ? 1 : 0;
    const float* x         = (const float*)d_in[0];
    const float* enc_out   = (const float*)d_in[2];
    const float* enc_state = (const float*)d_in[4];
    const int*   ids       = (const int*)  d_in[5 + s];
    const float* W_ih      = (const float*)d_in[6 + s];
    const float* b_ih      = (const float*)d_in[8 + s];
    const float* b_hh      = (const float*)d_in[9 + s];
    const float* Wh_w      = (const float*)d_in[10 + s];
    const float* Wh_b      = (const float*)d_in[11 + s];
    const float* Ws_w      = (const float*)d_in[12 + s];
    const float* Ws_b      = (const float*)d_in[13 + s];
    const float* v         = (const float*)d_in[14 + s];
    const float* fc1_w     = (const float*)d_in[15 + s];
    const float* fc1_b     = (const float*)d_in[16 + s];
    const float* fc2_w     = (const float*)d_in[17 + s];
    const float* fc2_b     = (const float*)d_in[18 + s];
    const float* pg1       = (const float*)d_in[19 + s];
    const float* pg2       = (const float*)d_in[20 + s];
    const float* pg3       = (const float*)d_in[21 + s];
    float* out = (float*)d_out;

    void *p_fc2w, *p_wih, *p_catw, *p_fc1w, *p_xh, *p_cat, *p_decin, *p_hid;
    void *p_gates, *p_h, *p_e, *p_att, *p_gen;
    cudaGetSymbolAddress(&p_fc2w, g_fc2w_h);
    cudaGetSymbolAddress(&p_wih, g_wih_h);
    cudaGetSymbolAddress(&p_catw, g_catw_h);
    cudaGetSymbolAddress(&p_fc1w, g_fc1w_h);
    cudaGetSymbolAddress(&p_xh, g_x_h);
    cudaGetSymbolAddress(&p_cat, g_cat_h);
    cudaGetSymbolAddress(&p_decin, g_decin_h);
    cudaGetSymbolAddress(&p_hid, g_hidden_h);
    cudaGetSymbolAddress(&p_gates, g_gates);
    cudaGetSymbolAddress(&p_h, g_hbuf);
    cudaGetSymbolAddress(&p_e, g_e);
    cudaGetSymbolAddress(&p_att, g_att);
    cudaGetSymbolAddress(&p_gen, g_gen);
    __half* fc2w_h = (__half*)p_fc2w;
    __half* wih_h  = (__half*)p_wih;
    __half* catw_h = (__half*)p_catw;
    __half* fc1w_h = (__half*)p_fc1w;
    __half* x_h    = (__half*)p_xh;
    __half* cat_h  = (__half*)p_cat;
    __half* decin_h= (__half*)p_decin;
    __half* hid_h  = (__half*)p_hid;
    float* gates   = (float*)p_gates;
    float* h       = (float*)p_h;
    float* e       = (float*)p_e;
    float* att     = (float*)p_att;
    float* gen     = (float*)p_gen;

    cudaFuncSetAttribute(hgemm, cudaFuncAttributeMaxDynamicSharedMemorySize, HG_SMEM);

    // ---- fp32 -> fp16 conversions (weights + x) ----
    f2h<<<(BATCH * IDIM / 8 + 255) / 256, 256>>>(x, x_h, BATCH * IDIM);
    f2h<<<(2048 * IDIM / 8 + 255) / 256, 256>>>(W_ih, wih_h, 2048 * IDIM);
    pack_catw<<<ADIM, 128>>>(Wh_w, Ws_w, catw_h);
    f2h<<<(1024 * 912 / 8 + 255) / 256, 256>>>(fc1_w, fc1w_h, 1024 * 912);
    {
        int n = VDIM * 1024;
        f2h<<<(n / 8 + 255) / 256, 256>>>(fc2_w, fc2w_h, n);
    }

    // 1) gates = x0 @ W_ih^T + b_ih + b_hh        (256 x 2048, K=256)
    hgemm<<<dim3(2, 16), 256, HG_SMEM>>>(x_h, wih_h, b_ih, b_hh,
                                         gates, 2048, IDIM, 2048, 0, 0);
    // 2) h, decin[:,400:], cat=[es|h]
    lstm_h_kernel<<<512, 256>>>(gates, enc_state, h, decin_h, cat_h);
    // 3) e = tanh(cat @ catw^T + Wh_b + Ws_b)     (256 x 400, K=1024)
    hgemm<<<dim3(2, 4), 256, HG_SMEM>>>(cat_h, catw_h, Wh_b, Ws_b,
                                        e, ADIM, 1024, ADIM, 1, 0);
    // 4) attention softmax + context + gen (fused)
    attn_context_gen<<<256, 512>>>(e, v, enc_out, h, x, pg1, pg2, pg3,
                                   att, decin_h, gen);
    // 5) hidden = decin @ fc1_w^T + fc1_b         (256 x 1024, K=912) -> fp16
    hgemm<<<dim3(2, 8), 256, HG_SMEM>>>(decin_h, fc1w_h, fc1_b, nullptr,
                                        hid_h, 1024, 912, 1024, 0, 1);
    // 6) logits -> out[:, :50000]                 (256 x 50000, K=1024)
    hgemm<<<dim3(2, 391), 256, HG_SMEM>>>(hid_h, fc2w_h, fc2_b, nullptr,
                                          out, VDIM, 1024, OUTC, 0, 0);
    // 7) softmax * gen, zero OOV, scatter-add copy distribution
    softmax_final<<<256, 1024>>>(out, gen, att, ids);

    (void)out_size; (void)n_in;
}